// round 7
// baseline (speedup 1.0000x reference)
#include <cuda_runtime.h>

// out_matrix, label_matrix: [n, n, B] fp32, n=64, B=256.
// loss = 2*S_tri + B*n*n*relu(m):
//   per (r, batch), strict upper triangle, t = m - (o_j-o_k)(l_j-l_k):
//   2*sum relu(t) = sum t + sum |t|;  sum t = 2016*m - (64*sum o*l - sum_o*sum_l)
// count = sum over (b,r) of [argmax_j out == argmax_j lab]
//
// Grid 1024 = 64 rows x 4 batch-chunks x 4 triangle-shares. Block 256 thr.
// Warp-share q = share*8 + warp owns rows {q, 63-q}: exactly 63 pairs.

#define NBLK 1024
typedef unsigned long long ull;

__device__ float    g_ploss[NBLK];
__device__ int      g_pcnt[NBLK];
__device__ unsigned g_done = 0;

static __device__ __forceinline__ ull add2(ull a, ull b) {
    ull d; asm("add.rn.f32x2 %0, %1, %2;" : "=l"(d) : "l"(a), "l"(b)); return d;
}
static __device__ __forceinline__ ull fma2(ull a, ull b, ull c) {
    ull d; asm("fma.rn.f32x2 %0, %1, %2, %3;" : "=l"(d) : "l"(a), "l"(b), "l"(c)); return d;
}
static __device__ __forceinline__ float2 up2(ull v) {
    float2 r; asm("mov.b64 {%0, %1}, %2;" : "=f"(r.x), "=f"(r.y) : "l"(v)); return r;
}
static __device__ __forceinline__ ull pk2(float x, float y) {
    ull v; asm("mov.b64 %0, {%1, %2};" : "=l"(v) : "f"(x), "f"(y)); return v;
}

#define SGN  0x8000000080000000ULL
#define ABSM 0x7fffffff7fffffffULL

__global__ void __launch_bounds__(256, 6)
fused_pair_loss_kernel(const float* __restrict__ outm,
                       const float* __restrict__ labm,
                       const float* __restrict__ marginp,
                       float* __restrict__ out, int out_size)
{
    __shared__ ull   so[64 * 32];     // packed out  [j][bpair]  16 KB
    __shared__ ull   snl[64 * 32];    // packed -lab [j][bpair]  16 KB
    __shared__ ull   red[256];        // reduction scratch        2 KB
    __shared__ float fredf[256];
    __shared__ int   ired[256];
    __shared__ int   scnt[2];
    __shared__ int   sdone;

    const int bid   = blockIdx.x;
    const int r     = bid >> 4;              // 0..63
    const int bc    = ((bid >> 2) & 3) * 64; // batch base
    const int share = bid & 3;               // triangle share 0..3
    const int tid   = threadIdx.x;
    const int lane  = tid & 31;
    const int w     = tid >> 5;              // 0..7
    const float margin = __ldg(marginp);
    const ull m2 = pk2(margin, margin);

    // Stage row r for 64 batches (coalesced float2 loads).
    for (int idx = tid; idx < 64 * 32; idx += 256) {
        const int j = idx >> 5, p = idx & 31;
        const int g = (r * 64 + j) * 256 + bc + 2 * p;
        const float2 o = *(const float2*)(outm + g);
        const float2 l = *(const float2*)(labm + g);
        so[idx]  = pk2(o.x, o.y);
        snl[idx] = pk2(-l.x, -l.y);
    }
    __syncthreads();

    // This warp owns rows jl = q and jh = 63-q.
    const int q  = share * 8 + w;       // 0..31
    const int jl = q;
    const int jh = 63 - q;

    const ull ojn0 = so [jl * 32 + lane] ^ SGN;   // -o_jl
    const ull ljp0 = snl[jl * 32 + lane] ^ SGN;   // +l_jl
    const ull ojn1 = so [jh * 32 + lane] ^ SGN;   // -o_jh
    const ull ljp1 = snl[jh * 32 + lane] ^ SGN;   // +l_jh

    // Static pair (jl, jh).
    ull acc0 = fma2(add2(ojn0, ojn1 ^ SGN), add2(ljp0, ljp1 ^ SGN), m2) & ABSM;
    ull acc1 = 0, acc2 = 0, acc3 = 0;

    // A: pairs (jl, k), k in [jl+1, jh-1]. Trip = 62-2q (even, may be 0).
    {
        const ull* pso = so  + (jl + 1) * 32 + lane;
        const ull* psl = snl + (jl + 1) * 32 + lane;
        int trip = 62 - 2 * q;
        #pragma unroll 2
        for (int i = 0; i < trip; i += 2) {
            const ull okA  = pso[0],  okB  = pso[32];
            const ull nlkA = psl[0],  nlkB = psl[32];
            const ull tA = fma2(add2(okA, ojn0), add2(ljp0, nlkA), m2);
            const ull tB = fma2(add2(okB, ojn0), add2(ljp0, nlkB), m2);
            acc0 = add2(acc0, tA & ABSM);
            acc3 = add2(acc3, tB & ABSM);
            pso += 64; psl += 64;
        }
    }

    // B: pairs (jl, k) and (jh, k), k in [jh+1, 63]. Trip = q.
    {
        const ull* pso = so  + (jh + 1) * 32 + lane;
        const ull* psl = snl + (jh + 1) * 32 + lane;
        #pragma unroll 2
        for (int i = 0; i < q; i++) {
            const ull ok  = pso[0];
            const ull nlk = psl[0];
            const ull t0 = fma2(add2(ok, ojn0), add2(ljp0, nlk), m2);
            const ull t1 = fma2(add2(ok, ojn1), add2(ljp1, nlk), m2);
            acc1 = add2(acc1, t0 & ABSM);
            acc2 = add2(acc2, t1 & ABSM);
            pso += 32; psl += 32;
        }
    }

    // Analytic sum-t term: only share-0 blocks (block-uniform branch).
    // Per packed-batch lane: A = 2016*m - 64*sum(o*l) + (sum o)(sum l).
    ull a_ns = 0, a_sO = 0, a_sNL = 0;
    if (share == 0) {
        ull nsol = 0, sO = 0, sNL = 0;        // nsol = -sum o*l
        #pragma unroll
        for (int i = 0; i < 8; i++) {
            const ull o  = so [(w * 8 + i) * 32 + lane];
            const ull nl = snl[(w * 8 + i) * 32 + lane];
            nsol = fma2(o, nl, nsol);
            sO   = add2(sO, o);
            sNL  = add2(sNL, nl);
        }
        // Three tree passes through the shared scratch.
        red[tid] = nsol; __syncthreads();
        if (tid < 128) red[tid] = add2(red[tid], red[tid + 128]); __syncthreads();
        if (tid < 64)  red[tid] = add2(red[tid], red[tid + 64]);  __syncthreads();
        if (tid < 32)  a_ns = add2(red[tid], red[tid + 32]);      __syncthreads();
        red[tid] = sO; __syncthreads();
        if (tid < 128) red[tid] = add2(red[tid], red[tid + 128]); __syncthreads();
        if (tid < 64)  red[tid] = add2(red[tid], red[tid + 64]);  __syncthreads();
        if (tid < 32)  a_sO = add2(red[tid], red[tid + 32]);      __syncthreads();
        red[tid] = sNL; __syncthreads();
        if (tid < 128) red[tid] = add2(red[tid], red[tid + 128]); __syncthreads();
        if (tid < 64)  red[tid] = add2(red[tid], red[tid + 64]);  __syncthreads();
        if (tid < 32)  a_sNL = add2(red[tid], red[tid + 32]);     __syncthreads();
    }

    // Argmax-equality: only share-1 blocks, warps 0-1 (one lane per batch).
    if (share == 1 && w < 2) {
        const int bl = w * 32 + lane;
        const float* sof = (const float*)so;
        const float* snf = (const float*)snl;
        float ob = sof[bl]; int oi = 0;
        float lb = snf[bl]; int li = 0;      // snl negated -> strict argmin
        for (int k = 1; k < 64; k++) {
            const float ov = sof[k * 64 + bl];
            if (ov > ob) { ob = ov; oi = k; }
            const float lv = snf[k * 64 + bl];
            if (lv < lb) { lb = lv; li = k; }
        }
        const unsigned ball = __ballot_sync(0xffffffffu, oi == li);
        if (lane == 0) scnt[w] = __popc(ball);
    }

    // Packed |t| reduction across 8 warps (fixed order, deterministic).
    red[tid] = add2(add2(acc0, acc1), add2(acc2, acc3));
    __syncthreads();
    if (tid < 128) red[tid] = add2(red[tid], red[tid + 128]);
    __syncthreads();
    if (tid < 64)  red[tid] = add2(red[tid], red[tid + 64]);
    __syncthreads();

    float bl_loss = 0.f;
    if (tid < 32) {
        ull s = add2(red[tid], red[tid + 32]);
        if (share == 0) {
            const ull c64   = pk2(64.f, 64.f);
            const ull m2016 = pk2(2016.f * margin, 2016.f * margin);
            ull A = fma2(c64, a_ns, m2016);       // 2016m - 64*sum(o*l)
            A = fma2(a_sO, a_sNL ^ SGN, A);       // + (sum o)(sum l)
            s = add2(s, A);
        }
        const float2 f = up2(s);
        float v = f.x + f.y;
        v += __shfl_down_sync(0xffffffffu, v, 16);
        v += __shfl_down_sync(0xffffffffu, v, 8);
        v += __shfl_down_sync(0xffffffffu, v, 4);
        v += __shfl_down_sync(0xffffffffu, v, 2);
        v += __shfl_down_sync(0xffffffffu, v, 1);
        bl_loss = v;
    }

    if (tid == 0) {
        g_ploss[bid] = bl_loss;
        g_pcnt[bid]  = (share == 1) ? (scnt[0] + scnt[1]) : 0;
        __threadfence();
        const unsigned t = atomicAdd(&g_done, 1u);
        sdone = (t == NBLK - 1);
    }
    __syncthreads();
    if (!sdone) return;

    // Last block: deterministic final reduce over 1024 partials.
    __threadfence();
    fredf[tid] = ((g_ploss[tid]       + g_ploss[tid + 256]) +
                  (g_ploss[tid + 512] + g_ploss[tid + 768]));
    ired[tid]  = g_pcnt[tid] + g_pcnt[tid + 256] +
                 g_pcnt[tid + 512] + g_pcnt[tid + 768];
    __syncthreads();
    #pragma unroll
    for (int s = 128; s > 0; s >>= 1) {
        if (tid < s) { fredf[tid] += fredf[tid + s]; ired[tid] += ired[tid + s]; }
        __syncthreads();
    }
    if (tid == 0) {
        // + diagonal: B*n*n terms of relu(margin)
        out[0] = fredf[0] + 1048576.f * fmaxf(margin, 0.f);
        if (out_size > 1) out[1] = (float)ired[0];
        g_done = 0;               // reset for next graph replay
    }
}

extern "C" void kernel_launch(void* const* d_in, const int* in_sizes, int n_in,
                              void* d_out, int out_size)
{
    const float* outm    = (const float*)d_in[0];
    const float* labm    = (const float*)d_in[1];
    const float* marginp = (const float*)d_in[2];
    (void)in_sizes; (void)n_in;

    fused_pair_loss_kernel<<<NBLK, 256>>>(outm, labm, marginp,
                                          (float*)d_out, out_size);
}

// round 9
// speedup vs baseline: 1.9828x; 1.9828x over previous
#include <cuda_runtime.h>

// out_matrix, label_matrix: [n, n, B] fp32, n=64, B=256.
// t(j,k) = m - (o_j-o_k)(l_j-l_k), symmetric in (j,k).
// Over the strict upper triangle: 2*sum relu(t) = sum t + sum |t|,
//   sum t = 2016*m - (64*sum_j o_j l_j - (sum o)(sum l))  (analytic, O(n))
// loss = [sum t + sum |t|] + B*n*n*relu(m)
// count = sum over (b,r) of [argmax_j out == argmax_j lab]
//
// Grid 256 = 64 rows x 4 batch-chunks of 64. Block 512 threads (16 warps).
// Warp w owns rows {2w, 2w+1, 62-2w, 63-2w}: 6 static pairs + C loop
// + D loop = 126 packed pairs, exactly uniform across warps.
// SMEM layout interleaves k-pairs so one LDS.128 yields 2 consecutive k.

#define NBLOCKS 256
typedef unsigned long long ull;

__device__ float    g_ploss[NBLOCKS];
__device__ int      g_pcnt[NBLOCKS];
__device__ unsigned g_done = 0;

static __device__ __forceinline__ ull add2(ull a, ull b) {
    ull d; asm("add.rn.f32x2 %0, %1, %2;" : "=l"(d) : "l"(a), "l"(b)); return d;
}
static __device__ __forceinline__ ull fma2(ull a, ull b, ull c) {
    ull d; asm("fma.rn.f32x2 %0, %1, %2, %3;" : "=l"(d) : "l"(a), "l"(b), "l"(c)); return d;
}
static __device__ __forceinline__ float2 up2(ull v) {
    float2 r; asm("mov.b64 {%0, %1}, %2;" : "=f"(r.x), "=f"(r.y) : "l"(v)); return r;
}
static __device__ __forceinline__ ull pk2(float x, float y) {
    ull v; asm("mov.b64 %0, {%1, %2};" : "=l"(v) : "f"(x), "f"(y)); return v;
}

#define SGN  0x8000000080000000ULL
#define ABSM 0x7fffffff7fffffffULL

// smem index of (row k, packed-batch lane p): kpair-interleaved so that
// [ (k,p) , (k+1,p) ] are 16B-adjacent -> one LDS.128 per array per k-pair.
#define SIDX(k, p) (((k) >> 1) * 64 + (p) * 2 + ((k) & 1))

__global__ void __launch_bounds__(512, 2)
fused_pair_loss_kernel(const float* __restrict__ outm,
                       const float* __restrict__ labm,
                       const float* __restrict__ marginp,
                       float* __restrict__ out, int out_size)
{
    __shared__ ull   so[64 * 32];     // packed out, kpair-interleaved  16 KB
    __shared__ ull   snl[64 * 32];    // packed -lab                    16 KB
    __shared__ ull   pd_sol[512];     // per-thread dot partials
    __shared__ ull   pd_so[512];
    __shared__ ull   pd_sl[512];
    __shared__ ull   red[512];
    __shared__ float fredf[256];
    __shared__ int   ired[256];
    __shared__ int   scnt[2];
    __shared__ int   sdone;

    const int bid  = blockIdx.x;
    const int r    = bid >> 2;              // row 0..63
    const int bc   = (bid & 3) * 64;        // batch-chunk base
    const int tid  = threadIdx.x;
    const int lane = tid & 31;
    const int w    = tid >> 5;              // warp role 0..15
    const float margin = __ldg(marginp);
    const ull m2 = pk2(margin, margin);

    // Stage row r for 64 batches. Each thread handles one (kpair, p) slot:
    // two coalesced LDG.64 per array, one STS.128 per array. 2 iterations.
    for (int it = 0; it < 2; it++) {
        const int idx = tid + it * 512;          // 0..1023
        const int q = idx >> 5, p = idx & 31;    // kpair 0..31, lane 0..31
        const int g0 = (r * 64 + 2 * q) * 256 + bc + 2 * p;
        const ull o0 = *(const ull*)(outm + g0);
        const ull o1 = *(const ull*)(outm + g0 + 256);
        const ull l0 = *(const ull*)(labm + g0);
        const ull l1 = *(const ull*)(labm + g0 + 256);
        *(ulonglong2*)&so[q * 64 + p * 2]  = make_ulonglong2(o0, o1);
        *(ulonglong2*)&snl[q * 64 + p * 2] = make_ulonglong2(l0 ^ SGN, l1 ^ SGN);
    }
    __syncthreads();

    const int jl = 2 * w;
    const int jh = 62 - 2 * w;

    ull ojn[4], ljp[4];   // -o_row, +l_row for the 4 owned rows
    ojn[0] = so [SIDX(jl,     lane)] ^ SGN;
    ojn[1] = so [SIDX(jl + 1, lane)] ^ SGN;
    ojn[2] = so [SIDX(jh,     lane)] ^ SGN;
    ojn[3] = so [SIDX(jh + 1, lane)] ^ SGN;
    ljp[0] = snl[SIDX(jl,     lane)] ^ SGN;
    ljp[1] = snl[SIDX(jl + 1, lane)] ^ SGN;
    ljp[2] = snl[SIDX(jh,     lane)] ^ SGN;
    ljp[3] = snl[SIDX(jh + 1, lane)] ^ SGN;

    ull acc0 = 0, acc1 = 0, acc2 = 0, acc3 = 0;

    // 6 static pairs among owned rows (row[i1] < row[i2] always).
    #pragma unroll
    for (int i1 = 0; i1 < 4; i1++) {
        #pragma unroll
        for (int i2 = i1 + 1; i2 < 4; i2++) {
            const ull a = add2(ojn[i1], ojn[i2] ^ SGN);   // o_k - o_j
            const ull b = add2(ljp[i1], ljp[i2] ^ SGN);   // l_j - l_k
            acc0 = add2(acc0, fma2(a, b, m2) & ABSM);
        }
    }

    // Per-lane dot partials for the analytic term (4 owned rows).
    {
        ull nsol = 0, sO = 0, sL = 0;
        #pragma unroll
        for (int i = 0; i < 4; i++) {
            nsol = fma2(ojn[i], ljp[i], nsol);   // -sum o*l
            sO   = add2(sO, ojn[i]);             // -sum o
            sL   = add2(sL, ljp[i]);             // +sum l
        }
        pd_sol[tid] = nsol; pd_so[tid] = sO; pd_sl[tid] = sL;
    }

    // C: k in [jl+2, jh-1] -> pairs with the 2 low rows.
    // kpair range [w+1, 30-w], trip 30-2w (even). 4 pairs per iteration.
    {
        const ulonglong2* pso = (const ulonglong2*)&so [(w + 1) * 64 + lane * 2];
        const ulonglong2* psl = (const ulonglong2*)&snl[(w + 1) * 64 + lane * 2];
        const int trip = 30 - 2 * w;
        #pragma unroll 2
        for (int i = 0; i < trip; i++) {
            const ulonglong2 ok2 = pso[0];
            const ulonglong2 nl2 = psl[0];
            acc0 = add2(acc0, fma2(add2(ok2.x, ojn[0]), add2(ljp[0], nl2.x), m2) & ABSM);
            acc1 = add2(acc1, fma2(add2(ok2.y, ojn[0]), add2(ljp[0], nl2.y), m2) & ABSM);
            acc2 = add2(acc2, fma2(add2(ok2.x, ojn[1]), add2(ljp[1], nl2.x), m2) & ABSM);
            acc3 = add2(acc3, fma2(add2(ok2.y, ojn[1]), add2(ljp[1], nl2.y), m2) & ABSM);
            pso += 32; psl += 32;
        }
    }

    // D: k in [jh+2, 63] -> pairs with all 4 owned rows.
    // kpair range [32-w, 31], trip w. 8 pairs per iteration.
    {
        const ulonglong2* pso = (const ulonglong2*)&so [(32 - w) * 64 + lane * 2];
        const ulonglong2* psl = (const ulonglong2*)&snl[(32 - w) * 64 + lane * 2];
        const int trip = w;
        for (int i = 0; i < trip; i++) {
            const ulonglong2 ok2 = pso[0];
            const ulonglong2 nl2 = psl[0];
            acc0 = add2(acc0, fma2(add2(ok2.x, ojn[0]), add2(ljp[0], nl2.x), m2) & ABSM);
            acc1 = add2(acc1, fma2(add2(ok2.y, ojn[0]), add2(ljp[0], nl2.y), m2) & ABSM);
            acc2 = add2(acc2, fma2(add2(ok2.x, ojn[1]), add2(ljp[1], nl2.x), m2) & ABSM);
            acc3 = add2(acc3, fma2(add2(ok2.y, ojn[1]), add2(ljp[1], nl2.y), m2) & ABSM);
            acc0 = add2(acc0, fma2(add2(ok2.x, ojn[2]), add2(ljp[2], nl2.x), m2) & ABSM);
            acc1 = add2(acc1, fma2(add2(ok2.y, ojn[2]), add2(ljp[2], nl2.y), m2) & ABSM);
            acc2 = add2(acc2, fma2(add2(ok2.x, ojn[3]), add2(ljp[3], nl2.x), m2) & ABSM);
            acc3 = add2(acc3, fma2(add2(ok2.y, ojn[3]), add2(ljp[3], nl2.y), m2) & ABSM);
            pso += 32; psl += 32;
        }
    }

    // Argmax-equality (warps 0,1; one lane per batch; snl negated -> argmin).
    if (w < 2) {
        const int bl2 = lane;                // packed-lane, this warp's half
        const int half = w;                  // 0 -> .x batches, 1 -> .y? no:
        // one lane per batch: batch b = w*32 + lane. Its packed slot is
        // p = b >> 1, element = b & 1.
        const int b  = w * 32 + lane;
        const int p  = b >> 1;
        const int el = b & 1;
        float ob, lb; int oi = 0, li = 0;
        {
            const float2 o0 = up2(so [SIDX(0, p)]);
            const float2 l0 = up2(snl[SIDX(0, p)]);
            ob = el ? o0.y : o0.x;
            lb = el ? l0.y : l0.x;
        }
        for (int k = 1; k < 64; k++) {
            const float2 ov2 = up2(so [SIDX(k, p)]);
            const float2 lv2 = up2(snl[SIDX(k, p)]);
            const float ov = el ? ov2.y : ov2.x;
            const float lv = el ? lv2.y : lv2.x;
            if (ov > ob) { ob = ov; oi = k; }
            if (lv < lb) { lb = lv; li = k; }   // negated -> strict argmin
        }
        const unsigned ball = __ballot_sync(0xffffffffu, oi == li);
        if (lane == 0) scnt[w] = __popc(ball);
        (void)bl2; (void)half;
    }

    // Packed |t| reduction across 16 warps (fixed order, deterministic).
    red[tid] = add2(add2(acc0, acc1), add2(acc2, acc3));
    __syncthreads();
    if (tid < 256) red[tid] = add2(red[tid], red[tid + 256]);
    __syncthreads();
    if (tid < 128) red[tid] = add2(red[tid], red[tid + 128]);
    __syncthreads();
    if (tid < 64)  red[tid] = add2(red[tid], red[tid + 64]);
    __syncthreads();

    float bl_loss = 0.f;
    if (tid < 32) {
        ull s_abs = add2(red[tid], red[tid + 32]);
        ull ns = pd_sol[tid], on = pd_so[tid], sl = pd_sl[tid];
        #pragma unroll
        for (int ww = 1; ww < 16; ww++) {
            ns = add2(ns, pd_sol[ww * 32 + tid]);
            on = add2(on, pd_so[ww * 32 + tid]);
            sl = add2(sl,  pd_sl[ww * 32 + tid]);
        }
        const ull c64   = pk2(64.f, 64.f);
        const ull m2016 = pk2(2016.f * margin, 2016.f * margin);
        ull A = fma2(c64, ns, m2016);       // 2016m - 64*sum(o*l)
        A = fma2(on ^ SGN, sl, A);          // + (sum o)(sum l)
        const float2 f = up2(add2(s_abs, A));
        float v = f.x + f.y;
        v += __shfl_down_sync(0xffffffffu, v, 16);
        v += __shfl_down_sync(0xffffffffu, v, 8);
        v += __shfl_down_sync(0xffffffffu, v, 4);
        v += __shfl_down_sync(0xffffffffu, v, 2);
        v += __shfl_down_sync(0xffffffffu, v, 1);
        bl_loss = v;
    }

    if (tid == 0) {
        g_ploss[bid] = bl_loss;
        g_pcnt[bid]  = scnt[0] + scnt[1];
        __threadfence();
        const unsigned t = atomicAdd(&g_done, 1u);
        sdone = (t == NBLOCKS - 1);
    }
    __syncthreads();
    if (!sdone) return;

    // Last block: deterministic final reduce over the 256 block partials.
    __threadfence();
    if (tid < 256) { fredf[tid] = g_ploss[tid]; ired[tid] = g_pcnt[tid]; }
    __syncthreads();
    #pragma unroll
    for (int s = 128; s > 0; s >>= 1) {
        if (tid < s) { fredf[tid] += fredf[tid + s]; ired[tid] += ired[tid + s]; }
        __syncthreads();
    }
    if (tid == 0) {
        // + diagonal: B*n*n terms of relu(margin)
        out[0] = fredf[0] + 1048576.f * fmaxf(margin, 0.f);
        if (out_size > 1) out[1] = (float)ired[0];
        g_done = 0;               // reset for next graph replay
    }
}

extern "C" void kernel_launch(void* const* d_in, const int* in_sizes, int n_in,
                              void* d_out, int out_size)
{
    const float* outm    = (const float*)d_in[0];
    const float* labm    = (const float*)d_in[1];
    const float* marginp = (const float*)d_in[2];
    (void)in_sizes; (void)n_in;

    fused_pair_loss_kernel<<<NBLOCKS, 512>>>(outm, labm, marginp,
                                             (float*)d_out, out_size);
}